// round 1
// baseline (speedup 1.0000x reference)
#include <cuda_runtime.h>
#include <math.h>

#define BATCH 2
#define NPTS 4096
#define CH 256
#define NLAYER 4
#define FDIM 1024
#define CATDIM 1024
#define MROWS ((size_t)BATCH * NPTS)   // 8192 flattened rows
#define LN_EPS 1e-6f
#define ATTN_EPS 1e-9f

// ---------------- scratch (device globals: allocation-free rule) ------------
__device__ float g_T[BATCH * NPTS * CH];
__device__ float g_X[BATCH * NPTS * CH];
__device__ float g_Q[BATCH * NPTS * CH];
__device__ float g_K[BATCH * NPTS * CH];
__device__ float g_V[BATCH * NPTS * CH];
__device__ float g_O[BATCH * NPTS * CH];
__device__ float g_S[(size_t)BATCH * NPTS * NPTS];   // 134 MB raw QK^T scores
__device__ float g_rmax[BATCH * NPTS];
__device__ float g_rinv[BATCH * NPTS];
__device__ float g_colpart[8 * BATCH * NPTS];
__device__ float g_gate[BATCH * NPTS];
__device__ float g_cat[(size_t)BATCH * NPTS * CATDIM];

// ---------------- input projection: [B,N,3] @ [3,256] + b ------------------
__global__ void k_inproj(const float* __restrict__ in, const float* __restrict__ w0,
                         const float* __restrict__ b0) {
    int idx = blockIdx.x * 256 + threadIdx.x;          // < B*N*CH
    int c = idx & (CH - 1);
    int bn = idx >> 8;
    const float* xp = in + bn * 3;
    float acc = b0[c];
    acc = fmaf(xp[0], w0[c], acc);
    acc = fmaf(xp[1], w0[CH + c], acc);
    acc = fmaf(xp[2], w0[2 * CH + c], acc);
    g_T[idx] = acc;
}

// ---------------- LayerNorm over the points axis (per (b,c)) ----------------
// relu_mode==1: dst = relu(ln(src)) + resid, also scatter into g_cat at c_off
__global__ void k_ln(const float* __restrict__ src, float* __restrict__ dst,
                     const float* __restrict__ scale, const float* __restrict__ bias,
                     const float* __restrict__ resid, float* __restrict__ cat,
                     int c_off, int relu_mode) {
    int lane = threadIdx.x & 31, row = threadIdx.x >> 5;
    int c = blockIdx.x * 32 + lane;
    int b = blockIdx.y;
    const float* sp = src + (size_t)b * NPTS * CH + c;
    float s0 = 0.f, s1 = 0.f;
    for (int n = row; n < NPTS; n += 8) {
        float v = sp[(size_t)n * CH];
        s0 += v; s1 = fmaf(v, v, s1);
    }
    __shared__ float sh0[8][32], sh1[8][32];
    sh0[row][lane] = s0; sh1[row][lane] = s1;
    __syncthreads();
    float mu = 0.f, m2 = 0.f;
#pragma unroll
    for (int r = 0; r < 8; r++) { mu += sh0[r][lane]; m2 += sh1[r][lane]; }
    mu *= (1.0f / NPTS); m2 *= (1.0f / NPTS);
    float rstd = rsqrtf(m2 - mu * mu + LN_EPS);
    float a = scale[c] * rstd;
    float bb = bias[c] - mu * a;
    size_t base = (size_t)b * NPTS * CH + c;
    if (relu_mode) {
        for (int n = row; n < NPTS; n += 8) {
            size_t idx = base + (size_t)n * CH;
            float v = fmaxf(fmaf(src[idx], a, bb), 0.f) + resid[idx];
            dst[idx] = v;
            cat[((size_t)b * NPTS + n) * CATDIM + c_off + c] = v;
        }
    } else {
        for (int n = row; n < NPTS; n += 8) {
            size_t idx = base + (size_t)n * CH;
            dst[idx] = fmaf(src[idx], a, bb);
        }
    }
}

// ---------------- tiled SGEMM: C[M,Ncol] = A[M,K] @ W[K,Ncol] + bias --------
// BM=128 BN=64 BK=16, 256 threads, 8x4 per-thread register tile
__global__ void __launch_bounds__(256) k_sgemm(const float* __restrict__ A,
                                               const float* __restrict__ W,
                                               const float* __restrict__ bias,
                                               float* __restrict__ Cout,
                                               int M, int K, int Ncol) {
    __shared__ float As[16][132];   // transposed A tile, padded
    __shared__ float Ws[16][64];
    int t = threadIdx.x;
    int m0 = blockIdx.y * 128, n0 = blockIdx.x * 64;
    int tm = t >> 4, tn = t & 15;
    float acc[8][4];
#pragma unroll
    for (int i = 0; i < 8; i++)
#pragma unroll
        for (int j = 0; j < 4; j++) acc[i][j] = 0.f;

    for (int k0 = 0; k0 < K; k0 += 16) {
#pragma unroll
        for (int i = 0; i < 2; i++) {
            int s4 = t + i * 256;
            int row = s4 >> 2, kc = (s4 & 3) * 4;
            float4 v = *(const float4*)(A + (size_t)(m0 + row) * K + k0 + kc);
            As[kc + 0][row] = v.x; As[kc + 1][row] = v.y;
            As[kc + 2][row] = v.z; As[kc + 3][row] = v.w;
        }
        {
            int kr = t >> 4, nc = (t & 15) * 4;
            float4 v = *(const float4*)(W + (size_t)(k0 + kr) * Ncol + n0 + nc);
            *(float4*)&Ws[kr][nc] = v;
        }
        __syncthreads();
#pragma unroll
        for (int kk = 0; kk < 16; kk++) {
            float a[8], bv[4];
            *(float4*)&a[0] = *(const float4*)&As[kk][tm * 8];
            *(float4*)&a[4] = *(const float4*)&As[kk][tm * 8 + 4];
            *(float4*)&bv[0] = *(const float4*)&Ws[kk][tn * 4];
#pragma unroll
            for (int i = 0; i < 8; i++)
#pragma unroll
                for (int j = 0; j < 4; j++)
                    acc[i][j] = fmaf(a[i], bv[j], acc[i][j]);
        }
        __syncthreads();
    }
    int n = n0 + tn * 4;
    float b0 = bias[n], b1 = bias[n + 1], b2 = bias[n + 2], b3 = bias[n + 3];
#pragma unroll
    for (int i = 0; i < 8; i++) {
        int m = m0 + tm * 8 + i;
        float4 o;
        o.x = acc[i][0] + b0; o.y = acc[i][1] + b1;
        o.z = acc[i][2] + b2; o.w = acc[i][3] + b3;
        *(float4*)(Cout + (size_t)m * Ncol + n) = o;
    }
}

// ---------------- QK^T pass 1: store raw S, online row max / row sum --------
// block: 64 Q rows, loops all 4096 K rows in chunks of 128, k paneled by 64
__global__ void __launch_bounds__(256) k_qk() {
    extern __shared__ float smem[];
    float* Qs = smem;                 // [256][68] transposed Q tile
    float* Ks = smem + 256 * 68;      // [64][132] transposed K panel
    int t = threadIdx.x;
    int b = blockIdx.y;
    int m0 = blockIdx.x * 64;
    const float* Qb = g_Q + (size_t)b * NPTS * CH;
    const float* Kb = g_K + (size_t)b * NPTS * CH;
    float* Sb = g_S + (size_t)b * NPTS * NPTS;

    // load Q tile [64 x 256] transposed -> Qs[k][m]
#pragma unroll
    for (int i = 0; i < 16; i++) {
        int s4 = t + i * 256;
        int row = s4 >> 6, kc = (s4 & 63) * 4;
        float4 v = *(const float4*)(Qb + (size_t)(m0 + row) * CH + kc);
        Qs[(kc + 0) * 68 + row] = v.x; Qs[(kc + 1) * 68 + row] = v.y;
        Qs[(kc + 2) * 68 + row] = v.z; Qs[(kc + 3) * 68 + row] = v.w;
    }

    int tm = t >> 5, tn = t & 31;   // warp tm owns rows tm*8..+7; lanes split cols
    float mrow[8], lrow[8];
#pragma unroll
    for (int r = 0; r < 8; r++) { mrow[r] = -1e30f; lrow[r] = 0.f; }

    for (int n0 = 0; n0 < NPTS; n0 += 128) {
        float acc[8][4];
#pragma unroll
        for (int i = 0; i < 8; i++)
#pragma unroll
            for (int j = 0; j < 4; j++) acc[i][j] = 0.f;

        for (int kp = 0; kp < 4; kp++) {
            __syncthreads();
#pragma unroll
            for (int i = 0; i < 8; i++) {
                int s4 = t + i * 256;
                int row = s4 >> 4, kc = (s4 & 15) * 4;
                float4 v = *(const float4*)(Kb + (size_t)(n0 + row) * CH + kp * 64 + kc);
                Ks[(kc + 0) * 132 + row] = v.x; Ks[(kc + 1) * 132 + row] = v.y;
                Ks[(kc + 2) * 132 + row] = v.z; Ks[(kc + 3) * 132 + row] = v.w;
            }
            __syncthreads();
#pragma unroll 8
            for (int kk = 0; kk < 64; kk++) {
                int kg = kp * 64 + kk;
                float a[8], bv[4];
                *(float4*)&a[0] = *(const float4*)&Qs[kg * 68 + tm * 8];
                *(float4*)&a[4] = *(const float4*)&Qs[kg * 68 + tm * 8 + 4];
                *(float4*)&bv[0] = *(const float4*)&Ks[kk * 132 + tn * 4];
#pragma unroll
                for (int i = 0; i < 8; i++)
#pragma unroll
                    for (int j = 0; j < 4; j++)
                        acc[i][j] = fmaf(a[i], bv[j], acc[i][j]);
            }
        }
        // store raw scores
#pragma unroll
        for (int r = 0; r < 8; r++) {
            float4 v = make_float4(acc[r][0], acc[r][1], acc[r][2], acc[r][3]);
            *(float4*)(Sb + (size_t)(m0 + tm * 8 + r) * NPTS + n0 + tn * 4) = v;
        }
        // online softmax stats (per-warp allreduce; warp == one tm group)
#pragma unroll
        for (int r = 0; r < 8; r++) {
            float cm = fmaxf(fmaxf(acc[r][0], acc[r][1]), fmaxf(acc[r][2], acc[r][3]));
#pragma unroll
            for (int off = 16; off; off >>= 1)
                cm = fmaxf(cm, __shfl_xor_sync(0xffffffffu, cm, off));
            float mn = fmaxf(mrow[r], cm);
            float ps = __expf(acc[r][0] - mn) + __expf(acc[r][1] - mn) +
                       __expf(acc[r][2] - mn) + __expf(acc[r][3] - mn);
#pragma unroll
            for (int off = 16; off; off >>= 1)
                ps += __shfl_xor_sync(0xffffffffu, ps, off);
            lrow[r] = lrow[r] * __expf(mrow[r] - mn) + ps;
            mrow[r] = mn;
        }
    }
    if (tn == 0) {
#pragma unroll
        for (int r = 0; r < 8; r++) {
            int m = m0 + tm * 8 + r;
            g_rmax[b * NPTS + m] = mrow[r];
            g_rinv[b * NPTS + m] = 1.0f / lrow[r];
        }
    }
}

// ---------------- pass 2: column sums of softmax(S) -------------------------
__global__ void k_colsum() {
    __shared__ float sm[512], si[512];
    int t = threadIdx.x;
    int b = blockIdx.z;
    int ms = blockIdx.y * 512;
    for (int i = t; i < 512; i += 256) {
        sm[i] = g_rmax[b * NPTS + ms + i];
        si[i] = g_rinv[b * NPTS + ms + i];
    }
    __syncthreads();
    int n = blockIdx.x * 256 + t;
    const float* Sp = g_S + (size_t)b * NPTS * NPTS + (size_t)ms * NPTS + n;
    float acc = 0.f;
#pragma unroll 8
    for (int m = 0; m < 512; m++)
        acc = fmaf(__expf(Sp[(size_t)m * NPTS] - sm[m]), si[m], acc);
    g_colpart[(blockIdx.y * BATCH + b) * NPTS + n] = acc;
}

// gate[b,n] = c / (eps + c)
__global__ void k_gate() {
    int i = blockIdx.x * 256 + threadIdx.x;  // < BATCH*NPTS
    float c = 0.f;
#pragma unroll
    for (int y = 0; y < 8; y++) c += g_colpart[y * BATCH * NPTS + i];
    g_gate[i] = c / (ATTN_EPS + c);
}

// T = gate * V
__global__ void k_gatev() {
    int idx = blockIdx.x * 256 + threadIdx.x;  // < B*N*CH
    int bn = idx >> 8;
    g_T[idx] = g_gate[bn] * g_V[idx];
}

// ---------------------------------------------------------------------------
extern "C" void kernel_launch(void* const* d_in, const int* in_sizes, int n_in,
                              void* d_out, int out_size) {
    const float* inp  = (const float*)d_in[0];
    const float* w0   = (const float*)d_in[1];
    const float* b0   = (const float*)d_in[2];
    const float* ln0s = (const float*)d_in[3];
    const float* ln0b = (const float*)d_in[4];
    const float* w1   = (const float*)d_in[5];
    const float* b1   = (const float*)d_in[6];
    const float* ln1s = (const float*)d_in[7];
    const float* ln1b = (const float*)d_in[8];
    const float* wq   = (const float*)d_in[9];
    const float* bq   = (const float*)d_in[10];
    const float* wk   = (const float*)d_in[11];
    const float* bk   = (const float*)d_in[12];
    const float* wv   = (const float*)d_in[13];
    const float* bv   = (const float*)d_in[14];
    const float* wo   = (const float*)d_in[15];
    const float* bo   = (const float*)d_in[16];
    const float* alns = (const float*)d_in[17];
    const float* alnb = (const float*)d_in[18];
    const float* wf   = (const float*)d_in[19];
    const float* bf   = (const float*)d_in[20];

    float *X, *T, *Q, *K, *V, *O, *CAT;
    cudaGetSymbolAddress((void**)&X, g_X);
    cudaGetSymbolAddress((void**)&T, g_T);
    cudaGetSymbolAddress((void**)&Q, g_Q);
    cudaGetSymbolAddress((void**)&K, g_K);
    cudaGetSymbolAddress((void**)&V, g_V);
    cudaGetSymbolAddress((void**)&O, g_O);
    cudaGetSymbolAddress((void**)&CAT, g_cat);

    const size_t QK_SMEM = (256 * 68 + 64 * 132) * sizeof(float);  // ~103 KB
    cudaFuncSetAttribute(k_qk, cudaFuncAttributeMaxDynamicSharedMemorySize,
                         (int)QK_SMEM);

    dim3 lnGrid(CH / 32, BATCH);
    dim3 gemmC(CH / 64, MROWS / 128);      // 4 x 64
    dim3 gemmF(FDIM / 64, MROWS / 128);    // 16 x 64

    // pre-conv stack
    k_inproj<<<BATCH * NPTS * CH / 256, 256>>>(inp, w0, b0);                 // -> T
    k_ln<<<lnGrid, 256>>>(T, X, ln0s, ln0b, nullptr, nullptr, 0, 0);
    k_sgemm<<<gemmC, 256>>>(X, w1, b1, O, (int)MROWS, CH, CH);
    k_ln<<<lnGrid, 256>>>(O, X, ln1s, ln1b, nullptr, nullptr, 0, 0);

    for (int i = 0; i < NLAYER; i++) {
        const float* wqi = wq + (size_t)i * CH * CH;
        const float* wki = wk + (size_t)i * CH * CH;
        const float* wvi = wv + (size_t)i * CH * CH;
        const float* woi = wo + (size_t)i * CH * CH;
        k_sgemm<<<gemmC, 256>>>(X, wqi, bq + i * CH, Q, (int)MROWS, CH, CH);
        k_sgemm<<<gemmC, 256>>>(X, wki, bk + i * CH, K, (int)MROWS, CH, CH);
        k_sgemm<<<gemmC, 256>>>(X, wvi, bv + i * CH, V, (int)MROWS, CH, CH);
        k_qk<<<dim3(NPTS / 64, BATCH), 256, QK_SMEM>>>();
        k_colsum<<<dim3(NPTS / 256, 8, BATCH), 256>>>();
        k_gate<<<BATCH * NPTS / 256, 256>>>();
        k_gatev<<<BATCH * NPTS * CH / 256, 256>>>();                         // T = gate*V
        k_sgemm<<<gemmC, 256>>>(T, woi, bo + i * CH, O, (int)MROWS, CH, CH);
        k_ln<<<lnGrid, 256>>>(O, X, alns + i * CH, alnb + i * CH, X, CAT,
                              i * CH, 1);
    }

    k_sgemm<<<gemmF, 256>>>(CAT, wf, bf, (float*)d_out, (int)MROWS, CATDIM, FDIM);
}

// round 4
// speedup vs baseline: 2.5401x; 2.5401x over previous
#include <cuda_runtime.h>
#include <cuda_fp16.h>
#include <math.h>
#include <stdint.h>

#define BATCH 2
#define NPTS 4096
#define CH 256
#define NLAYER 4
#define FDIM 1024
#define CATDIM 1024
#define MROWS ((size_t)BATCH * NPTS)
#define LN_EPS 1e-6f
#define ATTN_EPS 1e-9f
#define LN_SPLIT 32

#define PART_BYTES 10240          // 128 rows * 80B (64B data + 16B pad)
#define STAGE_BYTES (4 * PART_BYTES)
#define MMA_SMEM (2 * STAGE_BYTES)   // 81920

// ---------------- scratch (device globals) ----------------------------------
__device__ float g_T[BATCH * NPTS * CH];     // inproj out
__device__ float g_X[BATCH * NPTS * CH];     // residual fp32
__device__ float g_V[BATCH * NPTS * CH];
__device__ float g_O[BATCH * NPTS * CH];
__device__ float g_S[(size_t)BATCH * NPTS * NPTS];
__device__ float g_pmax[BATCH * 32 * NPTS];
__device__ float g_psum[BATCH * 32 * NPTS];
__device__ float g_rmax[BATCH * NPTS];
__device__ float g_rinv[BATCH * NPTS];
__device__ float g_colpart[8 * BATCH * NPTS];
__device__ float g_gate[BATCH * NPTS];
__device__ float g_lnp0[LN_SPLIT * BATCH * CH];
__device__ float g_lnp1[LN_SPLIT * BATCH * CH];
__device__ float g_lncA[BATCH * CH];
__device__ float g_lncB[BATCH * CH];

// half-split operand buffers
__device__ __half g_Xh[MROWS * CH],  g_Xl[MROWS * CH];
__device__ __half g_Qh[MROWS * CH],  g_Ql[MROWS * CH];
__device__ __half g_Kh[MROWS * CH],  g_Kl[MROWS * CH];
__device__ __half g_Th[MROWS * CH],  g_Tl[MROWS * CH];
__device__ __half g_CATh[MROWS * CATDIM], g_CATl[MROWS * CATDIM];
__device__ __half g_Wqh[NLAYER * CH * CH], g_Wql[NLAYER * CH * CH];
__device__ __half g_Wkh[NLAYER * CH * CH], g_Wkl[NLAYER * CH * CH];
__device__ __half g_Wvh[NLAYER * CH * CH], g_Wvl[NLAYER * CH * CH];
__device__ __half g_Woh[NLAYER * CH * CH], g_Wol[NLAYER * CH * CH];
__device__ __half g_W1h[CH * CH], g_W1l[CH * CH];
__device__ __half g_Wfh[CATDIM * FDIM], g_Wfl[CATDIM * FDIM];

// ---------------- PTX helpers ------------------------------------------------
__device__ __forceinline__ uint32_t smem_u32(const void* p) {
    uint32_t a;
    asm("{ .reg .u64 t; cvta.to.shared.u64 t, %1; cvt.u32.u64 %0, t; }"
        : "=r"(a) : "l"(p));
    return a;
}
__device__ __forceinline__ void cpa(uint32_t dst, const void* src) {
    asm volatile("cp.async.cg.shared.global [%0], [%1], 16;"
                 :: "r"(dst), "l"(src));
}
#define CP_COMMIT() asm volatile("cp.async.commit_group;" ::: "memory")
#define CP_WAIT1() asm volatile("cp.async.wait_group 1;" ::: "memory")
#define CP_WAIT0() asm volatile("cp.async.wait_group 0;" ::: "memory")

#define LDSM4(r, addr)                                                          \
    asm volatile("ldmatrix.sync.aligned.m8n8.x4.shared.b16 {%0,%1,%2,%3}, [%4];"\
        : "=r"((r)[0]), "=r"((r)[1]), "=r"((r)[2]), "=r"((r)[3]) : "r"(addr))

#define MMA16(d, a, b0r, b1r)                                                   \
    asm volatile("mma.sync.aligned.m16n8k16.row.col.f32.f16.f16.f32 "           \
        "{%0,%1,%2,%3}, {%4,%5,%6,%7}, {%8,%9}, {%0,%1,%2,%3};"                 \
        : "+f"((d)[0]), "+f"((d)[1]), "+f"((d)[2]), "+f"((d)[3])                \
        : "r"((a)[0]), "r"((a)[1]), "r"((a)[2]), "r"((a)[3]), "r"(b0r), "r"(b1r))

__device__ __forceinline__ void split2(float v0, float v1, __half2& hi, __half2& lo) {
    __half h0 = __float2half_rn(v0), h1 = __float2half_rn(v1);
    hi = __halves2half2(h0, h1);
    lo = __halves2half2(__float2half_rn(v0 - __half2float(h0)),
                        __float2half_rn(v1 - __half2float(h1)));
}

// ---------------- input projection ------------------------------------------
__global__ void k_inproj(const float* __restrict__ in, const float* __restrict__ w0,
                         const float* __restrict__ b0) {
    int idx = blockIdx.x * 256 + threadIdx.x;
    int c = idx & (CH - 1);
    int bn = idx >> 8;
    const float* xp = in + bn * 3;
    float acc = b0[c];
    acc = fmaf(xp[0], w0[c], acc);
    acc = fmaf(xp[1], w0[CH + c], acc);
    acc = fmaf(xp[2], w0[2 * CH + c], acc);
    g_T[idx] = acc;
}

// ---------------- LayerNorm over points axis: stats / coef / apply ----------
__global__ void k_ln_stats(const float* __restrict__ src) {
    int t = threadIdx.x;
    int ci = t & 63, nr = t >> 6;
    int c = blockIdx.x * 64 + ci;
    int b = blockIdx.y, sp = blockIdx.z;
    const float* p = src + ((size_t)b * NPTS + sp * (NPTS / LN_SPLIT)) * CH + c;
    float s0 = 0.f, s1 = 0.f;
    for (int n = nr; n < NPTS / LN_SPLIT; n += 4) {
        float v = p[(size_t)n * CH];
        s0 += v; s1 = fmaf(v, v, s1);
    }
    __shared__ float sh0[4][64], sh1[4][64];
    sh0[nr][ci] = s0; sh1[nr][ci] = s1;
    __syncthreads();
    if (nr == 0) {
        float a0 = 0.f, a1 = 0.f;
#pragma unroll
        for (int r = 0; r < 4; r++) { a0 += sh0[r][ci]; a1 += sh1[r][ci]; }
        g_lnp0[(sp * BATCH + b) * CH + c] = a0;
        g_lnp1[(sp * BATCH + b) * CH + c] = a1;
    }
}

__global__ void k_ln_coef(const float* __restrict__ scale, const float* __restrict__ bias) {
    int t = threadIdx.x;               // 512 = B*C
    int c = t & (CH - 1);
    float s0 = 0.f, s1 = 0.f;
#pragma unroll
    for (int j = 0; j < LN_SPLIT; j++) {
        s0 += g_lnp0[j * BATCH * CH + t];
        s1 += g_lnp1[j * BATCH * CH + t];
    }
    float mu = s0 * (1.0f / NPTS), m2 = s1 * (1.0f / NPTS);
    float rstd = rsqrtf(m2 - mu * mu + LN_EPS);
    float a = scale[c] * rstd;
    g_lncA[t] = a;
    g_lncB[t] = bias[c] - mu * a;
}

// apply: y = ln(x) (optionally relu + resid); write optional fp32 + half split
__global__ void k_ln_apply(const float* __restrict__ src, float* __restrict__ dstF,
                           __half* __restrict__ dH, __half* __restrict__ dL,
                           int ldH, int coff, const float* __restrict__ resid,
                           int relu_mode) {
    int i4 = blockIdx.x * 256 + threadIdx.x;       // < B*N*CH/4
    int c4 = i4 & 63;
    int bn = i4 >> 6;
    int b = bn >> 12;
    float4 x = ((const float4*)src)[i4];
    float4 a = ((const float4*)g_lncA)[b * 64 + c4];
    float4 bb = ((const float4*)g_lncB)[b * 64 + c4];
    float4 y;
    y.x = fmaf(x.x, a.x, bb.x); y.y = fmaf(x.y, a.y, bb.y);
    y.z = fmaf(x.z, a.z, bb.z); y.w = fmaf(x.w, a.w, bb.w);
    if (relu_mode) {
        float4 r = ((const float4*)resid)[i4];
        y.x = fmaxf(y.x, 0.f) + r.x; y.y = fmaxf(y.y, 0.f) + r.y;
        y.z = fmaxf(y.z, 0.f) + r.z; y.w = fmaxf(y.w, 0.f) + r.w;
    }
    if (dstF) ((float4*)dstF)[i4] = y;
    __half2 h0, l0, h1, l1;
    split2(y.x, y.y, h0, l0);
    split2(y.z, y.w, h1, l1);
    size_t hidx = (size_t)bn * (ldH >> 2) + (coff >> 2) + c4;   // uint2 units
    uint2 hv, lv;
    hv.x = *(uint32_t*)&h0; hv.y = *(uint32_t*)&h1;
    lv.x = *(uint32_t*)&l0; lv.y = *(uint32_t*)&l1;
    ((uint2*)dH)[hidx] = hv;
    ((uint2*)dL)[hidx] = lv;
}

// ---------------- weight transpose + split: W[K][N] -> WT hi/lo [N][K] ------
__global__ void k_splitW(const float* __restrict__ W, __half* __restrict__ Whi,
                         __half* __restrict__ Wlo, int Kd, int Nd) {
    int e = blockIdx.x * 256 + threadIdx.x;
    int lz = blockIdx.y;
    const float* Wp = W + (size_t)lz * Kd * Nd;
    float x = Wp[e];
    int k = e / Nd, n = e - k * Nd;
    __half h = __float2half_rn(x);
    size_t o = (size_t)lz * Kd * Nd + (size_t)n * Kd + k;
    Whi[o] = h;
    Wlo[o] = __float2half_rn(x - __half2float(h));
}

// ---------------- unified fp16x3 tensor GEMM: C = A * B^T -------------------
// A: [M][K] halves hi/lo, ldA; B: [N][K] halves hi/lo, ldB=K.
// MODE 0: Cf = acc + bias (fp32). MODE 1: split(acc + bias) -> Chi/Clo.
// MODE 2: QK — raw S to g_S, row softmax partials to g_pmax/g_psum.
template <int MODE>
__global__ void __launch_bounds__(256, 1) k_mma(
    const __half* __restrict__ Ah, const __half* __restrict__ Al, int ldA,
    const __half* __restrict__ Bh, const __half* __restrict__ Bl, int ldB,
    const float* __restrict__ bias,
    float* __restrict__ Cf, __half* __restrict__ Chi, __half* __restrict__ Clo,
    int ldC, int K) {
    extern __shared__ char smraw[];
    uint32_t sb = smem_u32(smraw);
    int t = threadIdx.x, l = t & 31, wid = t >> 5;
    int wm = wid >> 2, wn = wid & 3;
    int m0 = blockIdx.y * 128, n0 = blockIdx.x * 128;
    size_t aoffG = (size_t)m0 * ldA, boffG = (size_t)n0 * ldB;
    if (MODE == 2) {
        size_t z = (size_t)blockIdx.z * NPTS * CH;
        aoffG += z; boffG += z;
    }
    const __half* gAh = Ah + aoffG;
    const __half* gAl = Al + aoffG;
    const __half* gBh = Bh + boffG;
    const __half* gBl = Bl + boffG;

    float acc[4][4][4];
#pragma unroll
    for (int i = 0; i < 4; i++)
#pragma unroll
        for (int j = 0; j < 4; j++)
#pragma unroll
            for (int r = 0; r < 4; r++) acc[i][j][r] = 0.f;

    int prow = t >> 1, pq0 = (t & 1) * 2;   // thread loads 2 chunks/part
#define PREFETCH(c) do {                                                        \
        uint32_t st_ = sb + (uint32_t)((c) & 1) * STAGE_BYTES;                  \
        int ko_ = (c) * 32;                                                     \
        _Pragma("unroll")                                                       \
        for (int i_ = 0; i_ < 2; i_++) {                                        \
            int q_ = pq0 + i_;                                                  \
            uint32_t d_ = st_ + prow * 80 + q_ * 16;                            \
            int go_ = ko_ + q_ * 8;                                             \
            cpa(d_,                 gAh + (size_t)prow * ldA + go_);            \
            cpa(d_ + PART_BYTES,    gAl + (size_t)prow * ldA + go_);            \
            cpa(d_ + 2*PART_BYTES,  gBh + (size_t)prow * ldB + go_);            \
            cpa(d_ + 3*PART_BYTES,  gBl + (size_t)prow * ldB + go_);            \
        }                                                                       \
    } while (0)

    PREFETCH(0);
    CP_COMMIT();
    int NC = K >> 5;
    for (int c = 0; c < NC; c++) {
        if (c + 1 < NC) {
            PREFETCH(c + 1);
            CP_COMMIT();
            CP_WAIT1();
        } else {
            CP_WAIT0();
        }
        __syncthreads();
        uint32_t st = sb + (uint32_t)(c & 1) * STAGE_BYTES;
#pragma unroll
        for (int s16 = 0; s16 < 2; s16++) {
            uint32_t ah[4][4], al[4][4], bh[2][4], bl[2][4];
            uint32_t aoff = (uint32_t)((wm * 64 + (l & 15)) * 80 + s16 * 32 +
                                       (l >> 4) * 16);
#pragma unroll
            for (int mt = 0; mt < 4; mt++) {
                LDSM4(ah[mt], st + aoff + mt * 16 * 80);
                LDSM4(al[mt], st + PART_BYTES + aoff + mt * 16 * 80);
            }
            int g = l >> 3;
            uint32_t boff = (uint32_t)((wn * 32 + ((g >> 1) << 3) + (l & 7)) * 80 +
                                       s16 * 32 + (g & 1) * 16);
#pragma unroll
            for (int p = 0; p < 2; p++) {
                LDSM4(bh[p], st + 2 * PART_BYTES + boff + p * 16 * 80);
                LDSM4(bl[p], st + 3 * PART_BYTES + boff + p * 16 * 80);
            }
#pragma unroll
            for (int mt = 0; mt < 4; mt++)
#pragma unroll
                for (int nt = 0; nt < 4; nt++) {
                    int p = nt >> 1, h = (nt & 1) * 2;
                    MMA16(acc[mt][nt], ah[mt], bh[p][h], bh[p][h + 1]);
                    MMA16(acc[mt][nt], ah[mt], bl[p][h], bl[p][h + 1]);
                    MMA16(acc[mt][nt], al[mt], bh[p][h], bh[p][h + 1]);
                }
        }
        __syncthreads();
    }
#undef PREFETCH

    if (MODE == 0 || MODE == 1) {
#pragma unroll
        for (int mt = 0; mt < 4; mt++)
#pragma unroll
            for (int hh = 0; hh < 2; hh++) {
                int row = m0 + wm * 64 + mt * 16 + (l >> 2) + hh * 8;
#pragma unroll
                for (int nt = 0; nt < 4; nt++) {
                    int n = n0 + wn * 32 + nt * 8 + 2 * (l & 3);
                    float v0 = acc[mt][nt][hh * 2] + bias[n];
                    float v1 = acc[mt][nt][hh * 2 + 1] + bias[n + 1];
                    if (MODE == 0) {
                        *(float2*)(Cf + (size_t)row * ldC + n) = make_float2(v0, v1);
                    } else {
                        __half2 hv, lv;
                        split2(v0, v1, hv, lv);
                        *(__half2*)(Chi + (size_t)row * ldC + n) = hv;
                        *(__half2*)(Clo + (size_t)row * ldC + n) = lv;
                    }
                }
            }
    } else {
        // MODE 2: stage raw S + per-row softmax partials
        float* stage = (float*)smraw;                       // [128][132]
        float* wmax = (float*)(smraw + 128 * 132 * 4);      // [128][4]
        float* wsum = wmax + 512;
#pragma unroll
        for (int mt = 0; mt < 4; mt++)
#pragma unroll
            for (int hh = 0; hh < 2; hh++) {
                int row = wm * 64 + mt * 16 + (l >> 2) + hh * 8;
                float vmax = -3.0e38f;
#pragma unroll
                for (int nt = 0; nt < 4; nt++) {
                    int cc = wn * 32 + nt * 8 + 2 * (l & 3);
                    float v0 = acc[mt][nt][hh * 2], v1 = acc[mt][nt][hh * 2 + 1];
                    stage[row * 132 + cc] = v0;
                    stage[row * 132 + cc + 1] = v1;
                    vmax = fmaxf(vmax, fmaxf(v0, v1));
                }
                float vsum = 0.f;
#pragma unroll
                for (int nt = 0; nt < 4; nt++) {
                    vsum += __expf(acc[mt][nt][hh * 2] - vmax);
                    vsum += __expf(acc[mt][nt][hh * 2 + 1] - vmax);
                }
#pragma unroll
                for (int off = 1; off <= 2; off <<= 1) {
                    float om = __shfl_xor_sync(0xffffffffu, vmax, off);
                    float os = __shfl_xor_sync(0xffffffffu, vsum, off);
                    float nm = fmaxf(vmax, om);
                    vsum = vsum * __expf(vmax - nm) + os * __expf(om - nm);
                    vmax = nm;
                }
                if ((l & 3) == 0) {
                    wmax[row * 4 + wn] = vmax;
                    wsum[row * 4 + wn] = vsum;
                }
            }
        __syncthreads();
        int z = blockIdx.z;
        if (t < 128) {
            float M = -3.0e38f;
#pragma unroll
            for (int w = 0; w < 4; w++) M = fmaxf(M, wmax[t * 4 + w]);
            float S = 0.f;
#pragma unroll
            for (int w = 0; w < 4; w++)
                S += wsum[t * 4 + w] * __expf(wmax[t * 4 + w] - M);
            g_pmax[(z * 32 + blockIdx.x) * NPTS + m0 + t] = M;
            g_psum[(z * 32 + blockIdx.x) * NPTS + m0 + t] = S;
        }
        float* Sb = g_S + (size_t)z * NPTS * NPTS;
#pragma unroll
        for (int i = 0; i < 16; i++) {     // 128 rows * 32 float4 = 4096 = 256*16
            int f4 = t + i * 256;
            int r = f4 >> 5, c4 = f4 & 31;
            *(float4*)(Sb + (size_t)(m0 + r) * NPTS + n0 + c4 * 4) =
                *(const float4*)&stage[r * 132 + c4 * 4];
        }
    }
}

// ---------------- combine row partials --------------------------------------
__global__ void k_rowstats() {
    int i = blockIdx.x * 256 + threadIdx.x;   // < B*N
    int b = i >> 12, m = i & (NPTS - 1);
    float mx = -3.0e38f;
#pragma unroll
    for (int j = 0; j < 32; j++)
        mx = fmaxf(mx, g_pmax[(b * 32 + j) * NPTS + m]);
    float s = 0.f;
#pragma unroll
    for (int j = 0; j < 32; j++)
        s += g_psum[(b * 32 + j) * NPTS + m] *
             __expf(g_pmax[(b * 32 + j) * NPTS + m] - mx);
    g_rmax[i] = mx;
    g_rinv[i] = 1.0f / s;
}

// ---------------- pass 2: column sums of softmax(S) -------------------------
__global__ void k_colsum() {
    __shared__ float sm[512], si[512];
    int t = threadIdx.x;
    int b = blockIdx.z;
    int ms = blockIdx.y * 512;
    for (int i = t; i < 512; i += 256) {
        sm[i] = g_rmax[b * NPTS + ms + i];
        si[i] = g_rinv[b * NPTS + ms + i];
    }
    __syncthreads();
    int n = blockIdx.x * 256 + t;
    const float* Sp = g_S + (size_t)b * NPTS * NPTS + (size_t)ms * NPTS + n;
    float acc = 0.f;
#pragma unroll 8
    for (int m = 0; m < 512; m++)
        acc = fmaf(__expf(Sp[(size_t)m * NPTS] - sm[m]), si[m], acc);
    g_colpart[(blockIdx.y * BATCH + b) * NPTS + n] = acc;
}

__global__ void k_gate() {
    int i = blockIdx.x * 256 + threadIdx.x;
    float c = 0.f;
#pragma unroll
    for (int y = 0; y < 8; y++) c += g_colpart[y * BATCH * NPTS + i];
    g_gate[i] = c / (ATTN_EPS + c);
}

// T = gate * V, split to halves
__global__ void k_gatev() {
    int i4 = blockIdx.x * 256 + threadIdx.x;       // < B*N*CH/4
    float gt = g_gate[i4 >> 6];
    float4 v = ((const float4*)g_V)[i4];
    __half2 h0, l0, h1, l1;
    split2(gt * v.x, gt * v.y, h0, l0);
    split2(gt * v.z, gt * v.w, h1, l1);
    uint2 hv, lv;
    hv.x = *(uint32_t*)&h0; hv.y = *(uint32_t*)&h1;
    lv.x = *(uint32_t*)&l0; lv.y = *(uint32_t*)&l1;
    ((uint2*)g_Th)[i4] = hv;
    ((uint2*)g_Tl)[i4] = lv;
}

// ---------------------------------------------------------------------------
extern "C" void kernel_launch(void* const* d_in, const int* in_sizes, int n_in,
                              void* d_out, int out_size) {
    const float* inp  = (const float*)d_in[0];
    const float* w0   = (const float*)d_in[1];
    const float* b0   = (const float*)d_in[2];
    const float* ln0s = (const float*)d_in[3];
    const float* ln0b = (const float*)d_in[4];
    const float* w1   = (const float*)d_in[5];
    const float* b1   = (const float*)d_in[6];
    const float* ln1s = (const float*)d_in[7];
    const float* ln1b = (const float*)d_in[8];
    const float* wq   = (const float*)d_in[9];
    const float* bq   = (const float*)d_in[10];
    const float* wk   = (const float*)d_in[11];
    const float* bk   = (const float*)d_in[12];
    const float* wv   = (const float*)d_in[13];
    const float* bv   = (const float*)d_in[14];
    const float* wo   = (const float*)d_in[15];
    const float* bo   = (const float*)d_in[16];
    const float* alns = (const float*)d_in[17];
    const float* alnb = (const float*)d_in[18];
    const float* wf   = (const float*)d_in[19];
    const float* bf   = (const float*)d_in[20];

    float *T, *X, *V, *O;
    __half *Xh, *Xl, *Qh, *Ql, *Kh, *Kl, *Th, *Tl, *CATh, *CATl;
    __half *Wqh, *Wql, *Wkh, *Wkl, *Wvh, *Wvl, *Woh, *Wol, *W1h, *W1l, *Wfh, *Wfl;
    cudaGetSymbolAddress((void**)&T, g_T);
    cudaGetSymbolAddress((void**)&X, g_X);
    cudaGetSymbolAddress((void**)&V, g_V);
    cudaGetSymbolAddress((void**)&O, g_O);
    cudaGetSymbolAddress((void**)&Xh, g_Xh);   cudaGetSymbolAddress((void**)&Xl, g_Xl);
    cudaGetSymbolAddress((void**)&Qh, g_Qh);   cudaGetSymbolAddress((void**)&Ql, g_Ql);
    cudaGetSymbolAddress((void**)&Kh, g_Kh);   cudaGetSymbolAddress((void**)&Kl, g_Kl);
    cudaGetSymbolAddress((void**)&Th, g_Th);   cudaGetSymbolAddress((void**)&Tl, g_Tl);
    cudaGetSymbolAddress((void**)&CATh, g_CATh); cudaGetSymbolAddress((void**)&CATl, g_CATl);
    cudaGetSymbolAddress((void**)&Wqh, g_Wqh); cudaGetSymbolAddress((void**)&Wql, g_Wql);
    cudaGetSymbolAddress((void**)&Wkh, g_Wkh); cudaGetSymbolAddress((void**)&Wkl, g_Wkl);
    cudaGetSymbolAddress((void**)&Wvh, g_Wvh); cudaGetSymbolAddress((void**)&Wvl, g_Wvl);
    cudaGetSymbolAddress((void**)&Woh, g_Woh); cudaGetSymbolAddress((void**)&Wol, g_Wol);
    cudaGetSymbolAddress((void**)&W1h, g_W1h); cudaGetSymbolAddress((void**)&W1l, g_W1l);
    cudaGetSymbolAddress((void**)&Wfh, g_Wfh); cudaGetSymbolAddress((void**)&Wfl, g_Wfl);

    cudaFuncSetAttribute(k_mma<0>, cudaFuncAttributeMaxDynamicSharedMemorySize, MMA_SMEM);
    cudaFuncSetAttribute(k_mma<1>, cudaFuncAttributeMaxDynamicSharedMemorySize, MMA_SMEM);
    cudaFuncSetAttribute(k_mma<2>, cudaFuncAttributeMaxDynamicSharedMemorySize, MMA_SMEM);

    dim3 lnStats(CH / 64, BATCH, LN_SPLIT);
    const int applyGrid = (int)(MROWS * CH / 4 / 256);
    dim3 gridC(CH / 128, (int)(MROWS / 128));        // (2, 64)
    dim3 gridQK(NPTS / 128, NPTS / 128, BATCH);      // (32, 32, 2)
    dim3 gridF(FDIM / 128, (int)(MROWS / 128));      // (8, 64)

    // weight transpose+splits
    k_splitW<<<dim3(CH * CH / 256, NLAYER), 256>>>(wq, Wqh, Wql, CH, CH);
    k_splitW<<<dim3(CH * CH / 256, NLAYER), 256>>>(wk, Wkh, Wkl, CH, CH);
    k_splitW<<<dim3(CH * CH / 256, NLAYER), 256>>>(wv, Wvh, Wvl, CH, CH);
    k_splitW<<<dim3(CH * CH / 256, NLAYER), 256>>>(wo, Woh, Wol, CH, CH);
    k_splitW<<<dim3(CH * CH / 256, 1), 256>>>(w1, W1h, W1l, CH, CH);
    k_splitW<<<dim3(CATDIM * FDIM / 256, 1), 256>>>(wf, Wfh, Wfl, CATDIM, FDIM);

    // pre-conv stack
    k_inproj<<<BATCH * NPTS * CH / 256, 256>>>(inp, w0, b0);
    k_ln_stats<<<lnStats, 256>>>(T);
    k_ln_coef<<<1, 512>>>(ln0s, ln0b);
    k_ln_apply<<<applyGrid, 256>>>(T, nullptr, Xh, Xl, CH, 0, nullptr, 0);
    k_mma<0><<<gridC, 256, MMA_SMEM>>>(Xh, Xl, CH, W1h, W1l, CH, b1,
                                       O, nullptr, nullptr, CH, CH);
    k_ln_stats<<<lnStats, 256>>>(O);
    k_ln_coef<<<1, 512>>>(ln1s, ln1b);
    k_ln_apply<<<applyGrid, 256>>>(O, X, Xh, Xl, CH, 0, nullptr, 0);

    for (int i = 0; i < NLAYER; i++) {
        const __half* Ahh = (i == 0) ? Xh : CATh + (size_t)(i - 1) * CH;
        const __half* All = (i == 0) ? Xl : CATl + (size_t)(i - 1) * CH;
        int ldA = (i == 0) ? CH : CATDIM;
        size_t wOff = (size_t)i * CH * CH;
        k_mma<1><<<gridC, 256, MMA_SMEM>>>(Ahh, All, ldA, Wqh + wOff, Wql + wOff,
                                           CH, bq + i * CH, nullptr, Qh, Ql, CH, CH);
        k_mma<1><<<gridC, 256, MMA_SMEM>>>(Ahh, All, ldA, Wkh + wOff, Wkl + wOff,
                                           CH, bk + i * CH, nullptr, Kh, Kl, CH, CH);
        k_mma<0><<<gridC, 256, MMA_SMEM>>>(Ahh, All, ldA, Wvh + wOff, Wvl + wOff,
                                           CH, bv + i * CH, V, nullptr, nullptr, CH, CH);
        k_mma<2><<<gridQK, 256, MMA_SMEM>>>(Qh, Ql, CH, Kh, Kl, CH, nullptr,
                                            nullptr, nullptr, nullptr, NPTS, CH);
        k_rowstats<<<BATCH * NPTS / 256, 256>>>();
        k_colsum<<<dim3(NPTS / 256, 8, BATCH), 256>>>();
        k_gate<<<BATCH * NPTS / 256, 256>>>();
        k_gatev<<<(int)(MROWS * CH / 4 / 256), 256>>>();
        k_mma<0><<<gridC, 256, MMA_SMEM>>>(Th, Tl, CH, Woh + wOff, Wol + wOff,
                                           CH, bo + i * CH, O, nullptr, nullptr, CH, CH);
        k_ln_stats<<<lnStats, 256>>>(O);
        k_ln_coef<<<1, 512>>>(alns + i * CH, alnb + i * CH);
        k_ln_apply<<<applyGrid, 256>>>(O, X, CATh, CATl, CATDIM, i * CH, X, 1);
    }

    k_mma<0><<<gridF, 256, MMA_SMEM>>>(CATh, CATl, CATDIM, Wfh, Wfl, CATDIM, bf,
                                       (float*)d_out, nullptr, nullptr, FDIM, CATDIM);
}

// round 6
// speedup vs baseline: 3.0660x; 1.2071x over previous
#include <cuda_runtime.h>
#include <cuda_fp16.h>
#include <math.h>
#include <stdint.h>

#define BATCH 2
#define NPTS 4096
#define CH 256
#define NLAYER 4
#define FDIM 1024
#define CATDIM 1024
#define MROWS ((size_t)BATCH * NPTS)
#define LN_EPS 1e-6f
#define ATTN_EPS 1e-9f
#define LN_SPLIT 32
#define PSCALE 4096.0f
#define INV_PSCALE (1.0f / 4096.0f)

#define PART_BYTES 10240            // 128 rows * 80B (64B data + 16B pad)
#define STAGE4 (4 * PART_BYTES)     // linear GEMM stage (Ah,Al,Bh,Bl)
#define STAGE3 (3 * PART_BYTES)     // QK stage (Ah,Bh,Bl)
#define MMA_SMEM4 (2 * STAGE4)      // 81920
#define MMA_SMEM3 (2 * STAGE3)      // 61440

// ---------------- scratch (device globals) ----------------------------------
__device__ float g_T[BATCH * NPTS * CH];
__device__ float g_X[BATCH * NPTS * CH];
__device__ float g_V[BATCH * NPTS * CH];
__device__ float g_O[BATCH * NPTS * CH];
__device__ __half g_P[(size_t)BATCH * NPTS * NPTS];   // 67MB: 4096*exp(S-tilemax)
__device__ float g_pmax[BATCH * 32 * NPTS];
__device__ float g_psum[BATCH * 32 * NPTS];
__device__ float g_f[BATCH * 32 * NPTS];              // exp(pmax-M)*rinv/4096
__device__ float g_colpart[8 * BATCH * NPTS];
__device__ float g_lnp0[LN_SPLIT * BATCH * CH];
__device__ float g_lnp1[LN_SPLIT * BATCH * CH];
__device__ float g_lncA[BATCH * CH];
__device__ float g_lncB[BATCH * CH];

// half-split operand buffers
__device__ __half g_Xh[MROWS * CH],  g_Xl[MROWS * CH];
__device__ __half g_Qh[MROWS * CH],  g_Ql[MROWS * CH];
__device__ __half g_Kh[MROWS * CH],  g_Kl[MROWS * CH];
__device__ __half g_Th[MROWS * CH],  g_Tl[MROWS * CH];
__device__ __half g_CATh[MROWS * CATDIM], g_CATl[MROWS * CATDIM];
__device__ __half g_Wqh[NLAYER * CH * CH], g_Wql[NLAYER * CH * CH];
__device__ __half g_Wkh[NLAYER * CH * CH], g_Wkl[NLAYER * CH * CH];
__device__ __half g_Wvh[NLAYER * CH * CH], g_Wvl[NLAYER * CH * CH];
__device__ __half g_Woh[NLAYER * CH * CH], g_Wol[NLAYER * CH * CH];
__device__ __half g_W1h[CH * CH], g_W1l[CH * CH];
__device__ __half g_Wfh[CATDIM * FDIM], g_Wfl[CATDIM * FDIM];

// ---------------- PTX helpers ------------------------------------------------
__device__ __forceinline__ uint32_t smem_u32(const void* p) {
    uint32_t a;
    asm("{ .reg .u64 t; cvta.to.shared.u64 t, %1; cvt.u32.u64 %0, t; }"
        : "=r"(a) : "l"(p));
    return a;
}
__device__ __forceinline__ void cpa(uint32_t dst, const void* src) {
    asm volatile("cp.async.cg.shared.global [%0], [%1], 16;"
                 :: "r"(dst), "l"(src));
}
#define CP_COMMIT() asm volatile("cp.async.commit_group;" ::: "memory")
#define CP_WAIT1() asm volatile("cp.async.wait_group 1;" ::: "memory")
#define CP_WAIT0() asm volatile("cp.async.wait_group 0;" ::: "memory")

#define LDSM4(r, addr)                                                          \
    asm volatile("ldmatrix.sync.aligned.m8n8.x4.shared.b16 {%0,%1,%2,%3}, [%4];"\
        : "=r"((r)[0]), "=r"((r)[1]), "=r"((r)[2]), "=r"((r)[3]) : "r"(addr))

#define MMA16(d, a, b0r, b1r)                                                   \
    asm volatile("mma.sync.aligned.m16n8k16.row.col.f32.f16.f16.f32 "           \
        "{%0,%1,%2,%3}, {%4,%5,%6,%7}, {%8,%9}, {%0,%1,%2,%3};"                 \
        : "+f"((d)[0]), "+f"((d)[1]), "+f"((d)[2]), "+f"((d)[3])                \
        : "r"((a)[0]), "r"((a)[1]), "r"((a)[2]), "r"((a)[3]), "r"(b0r), "r"(b1r))

__device__ __forceinline__ void split2(float v0, float v1, __half2& hi, __half2& lo) {
    __half h0 = __float2half_rn(v0), h1 = __float2half_rn(v1);
    hi = __halves2half2(h0, h1);
    lo = __halves2half2(__float2half_rn(v0 - __half2float(h0)),
                        __float2half_rn(v1 - __half2float(h1)));
}

// ---------------- input projection ------------------------------------------
__global__ void k_inproj(const float* __restrict__ in, const float* __restrict__ w0,
                         const float* __restrict__ b0) {
    int idx = blockIdx.x * 256 + threadIdx.x;
    int c = idx & (CH - 1);
    int bn = idx >> 8;
    const float* xp = in + bn * 3;
    float acc = b0[c];
    acc = fmaf(xp[0], w0[c], acc);
    acc = fmaf(xp[1], w0[CH + c], acc);
    acc = fmaf(xp[2], w0[2 * CH + c], acc);
    g_T[idx] = acc;
}

// ---------------- LayerNorm over points axis: stats / coef / apply ----------
__global__ void k_ln_stats(const float* __restrict__ src) {
    int t = threadIdx.x;
    int ci = t & 63, nr = t >> 6;
    int c = blockIdx.x * 64 + ci;
    int b = blockIdx.y, sp = blockIdx.z;
    const float* p = src + ((size_t)b * NPTS + sp * (NPTS / LN_SPLIT)) * CH + c;
    float s0 = 0.f, s1 = 0.f;
    for (int n = nr; n < NPTS / LN_SPLIT; n += 4) {
        float v = p[(size_t)n * CH];
        s0 += v; s1 = fmaf(v, v, s1);
    }
    __shared__ float sh0[4][64], sh1[4][64];
    sh0[nr][ci] = s0; sh1[nr][ci] = s1;
    __syncthreads();
    if (nr == 0) {
        float a0 = 0.f, a1 = 0.f;
#pragma unroll
        for (int r = 0; r < 4; r++) { a0 += sh0[r][ci]; a1 += sh1[r][ci]; }
        g_lnp0[(sp * BATCH + b) * CH + c] = a0;
        g_lnp1[(sp * BATCH + b) * CH + c] = a1;
    }
}

__global__ void k_ln_coef(const float* __restrict__ scale, const float* __restrict__ bias) {
    int t = threadIdx.x;               // 512 = B*C
    int c = t & (CH - 1);
    float s0 = 0.f, s1 = 0.f;
#pragma unroll
    for (int j = 0; j < LN_SPLIT; j++) {
        s0 += g_lnp0[j * BATCH * CH + t];
        s1 += g_lnp1[j * BATCH * CH + t];
    }
    float mu = s0 * (1.0f / NPTS), m2 = s1 * (1.0f / NPTS);
    float rstd = rsqrtf(m2 - mu * mu + LN_EPS);
    float a = scale[c] * rstd;
    g_lncA[t] = a;
    g_lncB[t] = bias[c] - mu * a;
}

__global__ void k_ln_apply(const float* __restrict__ src, float* __restrict__ dstF,
                           __half* __restrict__ dH, __half* __restrict__ dL,
                           int ldH, int coff, const float* __restrict__ resid,
                           int relu_mode) {
    int i4 = blockIdx.x * 256 + threadIdx.x;       // < B*N*CH/4
    int c4 = i4 & 63;
    int bn = i4 >> 6;
    int b = bn >> 12;
    float4 x = ((const float4*)src)[i4];
    float4 a = ((const float4*)g_lncA)[b * 64 + c4];
    float4 bb = ((const float4*)g_lncB)[b * 64 + c4];
    float4 y;
    y.x = fmaf(x.x, a.x, bb.x); y.y = fmaf(x.y, a.y, bb.y);
    y.z = fmaf(x.z, a.z, bb.z); y.w = fmaf(x.w, a.w, bb.w);
    if (relu_mode) {
        float4 r = ((const float4*)resid)[i4];
        y.x = fmaxf(y.x, 0.f) + r.x; y.y = fmaxf(y.y, 0.f) + r.y;
        y.z = fmaxf(y.z, 0.f) + r.z; y.w = fmaxf(y.w, 0.f) + r.w;
    }
    if (dstF) ((float4*)dstF)[i4] = y;
    __half2 h0, l0, h1, l1;
    split2(y.x, y.y, h0, l0);
    split2(y.z, y.w, h1, l1);
    size_t hidx = (size_t)bn * (ldH >> 2) + (coff >> 2) + c4;
    uint2 hv, lv;
    hv.x = *(uint32_t*)&h0; hv.y = *(uint32_t*)&h1;
    lv.x = *(uint32_t*)&l0; lv.y = *(uint32_t*)&l1;
    ((uint2*)dH)[hidx] = hv;
    ((uint2*)dL)[hidx] = lv;
}

// ---------------- weight transpose + split ----------------------------------
__global__ void k_splitW(const float* __restrict__ W, __half* __restrict__ Whi,
                         __half* __restrict__ Wlo, int Kd, int Nd) {
    int e = blockIdx.x * 256 + threadIdx.x;
    int lz = blockIdx.y;
    const float* Wp = W + (size_t)lz * Kd * Nd;
    float x = Wp[e];
    int k = e / Nd, n = e - k * Nd;
    __half h = __float2half_rn(x);
    size_t o = (size_t)lz * Kd * Nd + (size_t)n * Kd + k;
    Whi[o] = h;
    Wlo[o] = __float2half_rn(x - __half2float(h));
}

// ---------------- unified fp16 tensor GEMM: C = A * B^T ---------------------
// MODE 0: fp16x3, Cf = acc + bias (fp32). MODE 1: fp16x3, split -> Chi/Clo.
// MODE 2: QK 2-pass (A hi only): P = 4096*exp(S - tilemax) fp16 + row partials.
template <int MODE>
__global__ void __launch_bounds__(256, 1) k_mma(
    const __half* __restrict__ Ah, const __half* __restrict__ Al, int ldA,
    const __half* __restrict__ Bh, const __half* __restrict__ Bl, int ldB,
    const float* __restrict__ bias,
    float* __restrict__ Cf, __half* __restrict__ Chi, __half* __restrict__ Clo,
    int ldC, int K) {
    extern __shared__ char smraw[];
    uint32_t sb = smem_u32(smraw);
    int t = threadIdx.x, l = t & 31, wid = t >> 5;
    int wm = wid >> 2, wn = wid & 3;
    int m0 = blockIdx.y * 128, n0 = blockIdx.x * 128;
    size_t aoffG = (size_t)m0 * ldA, boffG = (size_t)n0 * ldB;
    if (MODE == 2) {
        size_t z = (size_t)blockIdx.z * NPTS * CH;
        aoffG += z; boffG += z;
    }
    const __half* gAh = Ah + aoffG;
    const __half* gAl = Al + aoffG;
    const __half* gBh = Bh + boffG;
    const __half* gBl = Bl + boffG;

    const int STAGE = (MODE == 2) ? STAGE3 : STAGE4;

    float acc[4][4][4];
#pragma unroll
    for (int i = 0; i < 4; i++)
#pragma unroll
        for (int j = 0; j < 4; j++)
#pragma unroll
            for (int r = 0; r < 4; r++) acc[i][j][r] = 0.f;

    int prow = t >> 1, pq0 = (t & 1) * 2;
#define PREFETCH(c) do {                                                        \
        uint32_t st_ = sb + (uint32_t)((c) & 1) * STAGE;                        \
        int ko_ = (c) * 32;                                                     \
        _Pragma("unroll")                                                       \
        for (int i_ = 0; i_ < 2; i_++) {                                        \
            int q_ = pq0 + i_;                                                  \
            uint32_t d_ = st_ + prow * 80 + q_ * 16;                            \
            int go_ = ko_ + q_ * 8;                                             \
            if (MODE == 2) {                                                    \
                cpa(d_,                gAh + (size_t)prow * ldA + go_);         \
                cpa(d_ + PART_BYTES,   gBh + (size_t)prow * ldB + go_);         \
                cpa(d_ + 2*PART_BYTES, gBl + (size_t)prow * ldB + go_);         \
            } else {                                                            \
                cpa(d_,                gAh + (size_t)prow * ldA + go_);         \
                cpa(d_ + PART_BYTES,   gAl + (size_t)prow * ldA + go_);         \
                cpa(d_ + 2*PART_BYTES, gBh + (size_t)prow * ldB + go_);         \
                cpa(d_ + 3*PART_BYTES, gBl + (size_t)prow * ldB + go_);         \
            }                                                                   \
        }                                                                       \
    } while (0)

    PREFETCH(0);
    CP_COMMIT();
    int NC = K >> 5;
    for (int c = 0; c < NC; c++) {
        if (c + 1 < NC) {
            PREFETCH(c + 1);
            CP_COMMIT();
            CP_WAIT1();
        } else {
            CP_WAIT0();
        }
        __syncthreads();
        uint32_t st = sb + (uint32_t)(c & 1) * STAGE;
#pragma unroll
        for (int s16 = 0; s16 < 2; s16++) {
            uint32_t aoff = (uint32_t)((wm * 64 + (l & 15)) * 80 + s16 * 32 +
                                       (l >> 4) * 16);
            int g = l >> 3;
            uint32_t boff = (uint32_t)((wn * 32 + ((g >> 1) << 3) + (l & 7)) * 80 +
                                       s16 * 32 + (g & 1) * 16);
            if (MODE == 2) {
                uint32_t ah[4][4], bh[2][4], bl[2][4];
#pragma unroll
                for (int mt = 0; mt < 4; mt++)
                    LDSM4(ah[mt], st + aoff + mt * 16 * 80);
#pragma unroll
                for (int p = 0; p < 2; p++) {
                    LDSM4(bh[p], st + PART_BYTES + boff + p * 16 * 80);
                    LDSM4(bl[p], st + 2 * PART_BYTES + boff + p * 16 * 80);
                }
#pragma unroll
                for (int mt = 0; mt < 4; mt++)
#pragma unroll
                    for (int nt = 0; nt < 4; nt++) {
                        int p = nt >> 1, h = (nt & 1) * 2;
                        MMA16(acc[mt][nt], ah[mt], bh[p][h], bh[p][h + 1]);
                        MMA16(acc[mt][nt], ah[mt], bl[p][h], bl[p][h + 1]);
                    }
            } else {
                uint32_t ah[4][4], al[4][4], bh[2][4], bl[2][4];
#pragma unroll
                for (int mt = 0; mt < 4; mt++) {
                    LDSM4(ah[mt], st + aoff + mt * 16 * 80);
                    LDSM4(al[mt], st + PART_BYTES + aoff + mt * 16 * 80);
                }
#pragma unroll
                for (int p = 0; p < 2; p++) {
                    LDSM4(bh[p], st + 2 * PART_BYTES + boff + p * 16 * 80);
                    LDSM4(bl[p], st + 3 * PART_BYTES + boff + p * 16 * 80);
                }
#pragma unroll
                for (int mt = 0; mt < 4; mt++)
#pragma unroll
                    for (int nt = 0; nt < 4; nt++) {
                        int p = nt >> 1, h = (nt & 1) * 2;
                        MMA16(acc[mt][nt], ah[mt], bh[p][h], bh[p][h + 1]);
                        MMA16(acc[mt][nt], ah[mt], bl[p][h], bl[p][h + 1]);
                        MMA16(acc[mt][nt], al[mt], bh[p][h], bh[p][h + 1]);
                    }
            }
        }
        __syncthreads();
    }
#undef PREFETCH

    if (MODE == 0 || MODE == 1) {
#pragma unroll
        for (int mt = 0; mt < 4; mt++)
#pragma unroll
            for (int hh = 0; hh < 2; hh++) {
                int row = m0 + wm * 64 + mt * 16 + (l >> 2) + hh * 8;
#pragma unroll
                for (int nt = 0; nt < 4; nt++) {
                    int n = n0 + wn * 32 + nt * 8 + 2 * (l & 3);
                    float v0 = acc[mt][nt][hh * 2] + bias[n];
                    float v1 = acc[mt][nt][hh * 2 + 1] + bias[n + 1];
                    if (MODE == 0) {
                        *(float2*)(Cf + (size_t)row * ldC + n) = make_float2(v0, v1);
                    } else {
                        __half2 hv, lv;
                        split2(v0, v1, hv, lv);
                        *(__half2*)(Chi + (size_t)row * ldC + n) = hv;
                        *(__half2*)(Clo + (size_t)row * ldC + n) = lv;
                    }
                }
            }
    } else {
        // MODE 2 epilogue: full tile rowmax -> P=4096*exp(S-max) fp16 -> global
        __half* pst = (__half*)smraw;                       // [128][136] halves
        float* wmaxs = (float*)(smraw + 36864);             // [128][4]
        float* wsums = wmaxs + 512;                         // [128][4]
        // 1) per-warp row max across this warp's 32 columns
#pragma unroll
        for (int mt = 0; mt < 4; mt++)
#pragma unroll
            for (int hh = 0; hh < 2; hh++) {
                int row = wm * 64 + mt * 16 + hh * 8 + (l >> 2);
                float vmax = -3.0e38f;
#pragma unroll
                for (int nt = 0; nt < 4; nt++)
                    vmax = fmaxf(vmax, fmaxf(acc[mt][nt][hh * 2],
                                             acc[mt][nt][hh * 2 + 1]));
#pragma unroll
                for (int off = 1; off <= 2; off <<= 1)
                    vmax = fmaxf(vmax, __shfl_xor_sync(0xffffffffu, vmax, off));
                if ((l & 3) == 0) wmaxs[row * 4 + wn] = vmax;
            }
        __syncthreads();
        // 2) exp against full tile max, stage fp16, accumulate row sums
#pragma unroll
        for (int mt = 0; mt < 4; mt++)
#pragma unroll
            for (int hh = 0; hh < 2; hh++) {
                int row = wm * 64 + mt * 16 + hh * 8 + (l >> 2);
                float M = fmaxf(fmaxf(wmaxs[row * 4], wmaxs[row * 4 + 1]),
                                fmaxf(wmaxs[row * 4 + 2], wmaxs[row * 4 + 3]));
                float s = 0.f;
#pragma unroll
                for (int nt = 0; nt < 4; nt++) {
                    float e0 = __expf(acc[mt][nt][hh * 2] - M) * PSCALE;
                    float e1 = __expf(acc[mt][nt][hh * 2 + 1] - M) * PSCALE;
                    s += e0 + e1;
                    *(__half2*)&pst[row * 136 + wn * 32 + nt * 8 + 2 * (l & 3)] =
                        __floats2half2_rn(e0, e1);
                }
#pragma unroll
                for (int off = 1; off <= 2; off <<= 1)
                    s += __shfl_xor_sync(0xffffffffu, s, off);
                if ((l & 3) == 0) wsums[row * 4 + wn] = s;
            }
        __syncthreads();
        int z = blockIdx.z;
        if (t < 128) {
            float M = fmaxf(fmaxf(wmaxs[t * 4], wmaxs[t * 4 + 1]),
                            fmaxf(wmaxs[t * 4 + 2], wmaxs[t * 4 + 3]));
            float S = (wsums[t * 4] + wsums[t * 4 + 1] + wsums[t * 4 + 2] +
                       wsums[t * 4 + 3]) * INV_PSCALE;
            g_pmax[(z * 32 + blockIdx.x) * NPTS + m0 + t] = M;
            g_psum[(z * 32 + blockIdx.x) * NPTS + m0 + t] = S;
        }
        __half* Pb = g_P + (size_t)z * NPTS * NPTS;
#pragma unroll
        for (int i = 0; i < 8; i++) {        // 2048 uint4 = 256 thr * 8
            int f = t + i * 256;
            int r = f >> 4, c8 = f & 15;     // 16 uint4 per 128-half row
            *(uint4*)(Pb + (size_t)(m0 + r) * NPTS + n0 + c8 * 8) =
                *(const uint4*)&pst[r * 136 + c8 * 8];
        }
    }
}

// ---------------- combine row partials, emit correction factors ------------
__global__ void k_rowstats() {
    int i = blockIdx.x * 256 + threadIdx.x;   // < B*N
    int b = i >> 12, m = i & (NPTS - 1);
    float pm[32];
    float mx = -3.0e38f;
#pragma unroll
    for (int j = 0; j < 32; j++) {
        pm[j] = g_pmax[(b * 32 + j) * NPTS + m];
        mx = fmaxf(mx, pm[j]);
    }
    float s = 0.f;
#pragma unroll
    for (int j = 0; j < 32; j++)
        s += g_psum[(b * 32 + j) * NPTS + m] * __expf(pm[j] - mx);
    float inv = INV_PSCALE / s;
#pragma unroll
    for (int j = 0; j < 32; j++)
        g_f[(b * 32 + j) * NPTS + m] = __expf(pm[j] - mx) * inv;
}

// ---------------- pass 2: column sums = fp16 GEMV ---------------------------
__global__ void k_colsum() {
    __shared__ float fs[512];
    int nt = blockIdx.x, mc = blockIdx.y, b = blockIdx.z, t = threadIdx.x;
    for (int i = t; i < 512; i += 128)
        fs[i] = g_f[(b * 32 + nt) * NPTS + mc * 512 + i];
    __syncthreads();
    int n = nt * 128 + t;
    const __half* P = g_P + (size_t)b * NPTS * NPTS + (size_t)(mc * 512) * NPTS + n;
    float a0 = 0.f, a1 = 0.f, a2 = 0.f, a3 = 0.f;
#pragma unroll 4
    for (int m = 0; m < 512; m += 4) {
        a0 = fmaf(__half2float(P[(size_t)(m + 0) * NPTS]), fs[m + 0], a0);
        a1 = fmaf(__half2float(P[(size_t)(m + 1) * NPTS]), fs[m + 1], a1);
        a2 = fmaf(__half2float(P[(size_t)(m + 2) * NPTS]), fs[m + 2], a2);
        a3 = fmaf(__half2float(P[(size_t)(m + 3) * NPTS]), fs[m + 3], a3);
    }
    g_colpart[(mc * BATCH + b) * NPTS + n] = (a0 + a1) + (a2 + a3);
}

// ---------------- gate + gate*V + split -------------------------------------
__global__ void k_gatev() {
    int i4 = blockIdx.x * 256 + threadIdx.x;       // < B*N*CH/4
    int bn = i4 >> 6;
    float c = 0.f;
#pragma unroll
    for (int y = 0; y < 8; y++) c += g_colpart[y * BATCH * NPTS + bn];
    float gt = c / (ATTN_EPS + c);
    float4 v = ((const float4*)g_V)[i4];
    __half2 h0, l0, h1, l1;
    split2(gt * v.x, gt * v.y, h0, l0);
    split2(gt * v.z, gt * v.w, h1, l1);
    uint2 hv, lv;
    hv.x = *(uint32_t*)&h0; hv.y = *(uint32_t*)&h1;
    lv.x = *(uint32_t*)&l0; lv.y = *(uint32_t*)&l1;
    ((uint2*)g_Th)[i4] = hv;
    ((uint2*)g_Tl)[i4] = lv;
}

// ---------------------------------------------------------------------------
extern "C" void kernel_launch(void* const* d_in, const int* in_sizes, int n_in,
                              void* d_out, int out_size) {
    const float* inp  = (const float*)d_in[0];
    const float* w0   = (const float*)d_in[1];
    const float* b0   = (const float*)d_in[2];
    const float* ln0s = (const float*)d_in[3];
    const float* ln0b = (const float*)d_in[4];
    const float* w1   = (const float*)d_in[5];
    const float* b1   = (const float*)d_in[6];
    const float* ln1s = (const float*)d_in[7];
    const float* ln1b = (const float*)d_in[8];
    const float* wq   = (const float*)d_in[9];
    const float* bq   = (const float*)d_in[10];
    const float* wk   = (const float*)d_in[11];
    const float* bk   = (const float*)d_in[12];
    const float* wv   = (const float*)d_in[13];
    const float* bv   = (const float*)d_in[14];
    const float* wo   = (const float*)d_in[15];
    const float* bo   = (const float*)d_in[16];
    const float* alns = (const float*)d_in[17];
    const float* alnb = (const float*)d_in[18];
    const float* wf   = (const float*)d_in[19];
    const float* bf   = (const float*)d_in[20];

    float *T, *X, *V, *O;
    __half *Xh, *Xl, *Qh, *Ql, *Kh, *Kl, *Th, *Tl, *CATh, *CATl;
    __half *Wqh, *Wql, *Wkh, *Wkl, *Wvh, *Wvl, *Woh, *Wol, *W1h, *W1l, *Wfh, *Wfl;
    cudaGetSymbolAddress((void**)&T, g_T);
    cudaGetSymbolAddress((void**)&X, g_X);
    cudaGetSymbolAddress((void**)&V, g_V);
    cudaGetSymbolAddress((void**)&O, g_O);
    cudaGetSymbolAddress((void**)&Xh, g_Xh);   cudaGetSymbolAddress((void**)&Xl, g_Xl);
    cudaGetSymbolAddress((void**)&Qh, g_Qh);   cudaGetSymbolAddress((void**)&Ql, g_Ql);
    cudaGetSymbolAddress((void**)&Kh, g_Kh);   cudaGetSymbolAddress((void**)&Kl, g_Kl);
    cudaGetSymbolAddress((void**)&Th, g_Th);   cudaGetSymbolAddress((void**)&Tl, g_Tl);
    cudaGetSymbolAddress((void**)&CATh, g_CATh); cudaGetSymbolAddress((void**)&CATl, g_CATl);
    cudaGetSymbolAddress((void**)&Wqh, g_Wqh); cudaGetSymbolAddress((void**)&Wql, g_Wql);
    cudaGetSymbolAddress((void**)&Wkh, g_Wkh); cudaGetSymbolAddress((void**)&Wkl, g_Wkl);
    cudaGetSymbolAddress((void**)&Wvh, g_Wvh); cudaGetSymbolAddress((void**)&Wvl, g_Wvl);
    cudaGetSymbolAddress((void**)&Woh, g_Woh); cudaGetSymbolAddress((void**)&Wol, g_Wol);
    cudaGetSymbolAddress((void**)&W1h, g_W1h); cudaGetSymbolAddress((void**)&W1l, g_W1l);
    cudaGetSymbolAddress((void**)&Wfh, g_Wfh); cudaGetSymbolAddress((void**)&Wfl, g_Wfl);

    cudaFuncSetAttribute(k_mma<0>, cudaFuncAttributeMaxDynamicSharedMemorySize, MMA_SMEM4);
    cudaFuncSetAttribute(k_mma<1>, cudaFuncAttributeMaxDynamicSharedMemorySize, MMA_SMEM4);
    cudaFuncSetAttribute(k_mma<2>, cudaFuncAttributeMaxDynamicSharedMemorySize, MMA_SMEM3);

    dim3 lnStats(CH / 64, BATCH, LN_SPLIT);
    const int applyGrid = (int)(MROWS * CH / 4 / 256);
    dim3 gridC(CH / 128, (int)(MROWS / 128));        // (2, 64)
    dim3 gridQK(NPTS / 128, NPTS / 128, BATCH);      // (32, 32, 2)
    dim3 gridF(FDIM / 128, (int)(MROWS / 128));      // (8, 64)

    // weight transpose+splits
    k_splitW<<<dim3(CH * CH / 256, NLAYER), 256>>>(wq, Wqh, Wql, CH, CH);
    k_splitW<<<dim3(CH * CH / 256, NLAYER), 256>>>(wk, Wkh, Wkl, CH, CH);
    k_splitW<<<dim3(CH * CH / 256, NLAYER), 256>>>(wv, Wvh, Wvl, CH, CH);
    k_splitW<<<dim3(CH * CH / 256, NLAYER), 256>>>(wo, Woh, Wol, CH, CH);
    k_splitW<<<dim3(CH * CH / 256, 1), 256>>>(w1, W1h, W1l, CH, CH);
    k_splitW<<<dim3(CATDIM * FDIM / 256, 1), 256>>>(wf, Wfh, Wfl, CATDIM, FDIM);

    // pre-conv stack
    k_inproj<<<BATCH * NPTS * CH / 256, 256>>>(inp, w0, b0);
    k_ln_stats<<<lnStats, 256>>>(T);
    k_ln_coef<<<1, 512>>>(ln0s, ln0b);
    k_ln_apply<<<applyGrid, 256>>>(T, nullptr, Xh, Xl, CH, 0, nullptr, 0);
    k_mma<0><<<gridC, 256, MMA_SMEM4>>>(Xh, Xl, CH, W1h, W1l, CH, b1,
                                        O, nullptr, nullptr, CH, CH);
    k_ln_stats<<<lnStats, 256>>>(O);
    k_ln_coef<<<1, 512>>>(ln1s, ln1b);
    k_ln_apply<<<applyGrid, 256>>>(O, X, Xh, Xl, CH, 0, nullptr, 0);

    for (int i = 0; i < NLAYER; i++) {
        const __half* Ahh = (i == 0) ? Xh : CATh + (size_t)(i - 1) * CH;
        const __half* All = (i == 0) ? Xl : CATl + (size_t)(i - 1) * CH;
        int ldA = (i == 0) ? CH : CATDIM;
        size_t wOff = (size_t)i * CH * CH;
        k_mma<1><<<gridC, 256, MMA_SMEM4>>>(Ahh, All, ldA, Wqh + wOff, Wql + wOff,
                                            CH, bq + i * CH, nullptr, Qh, Ql, CH, CH);
        k_mma<1><<<gridC, 256, MMA_SMEM4>>>(Ahh, All, ldA, Wkh + wOff, Wkl + wOff,
                                            CH, bk + i * CH, nullptr, Kh, Kl, CH, CH);
        k_mma<0><<<gridC, 256, MMA_SMEM4>>>(Ahh, All, ldA, Wvh + wOff, Wvl + wOff,
                                            CH, bv + i * CH, V, nullptr, nullptr, CH, CH);
        // QK: A = Q hi only (2-pass), B = K hi+lo
        k_mma<2><<<gridQK, 256, MMA_SMEM3>>>(Qh, Qh, CH, Kh, Kl, CH, nullptr,
                                             nullptr, nullptr, nullptr, NPTS, CH);
        k_rowstats<<<BATCH * NPTS / 256, 256>>>();
        k_colsum<<<dim3(32, 8, BATCH), 128>>>();
        k_gatev<<<(int)(MROWS * CH / 4 / 256), 256>>>();
        k_mma<0><<<gridC, 256, MMA_SMEM4>>>(Th, Tl, CH, Woh + wOff, Wol + wOff,
                                            CH, bo + i * CH, O, nullptr, nullptr, CH, CH);
        k_ln_stats<<<lnStats, 256>>>(O);
        k_ln_coef<<<1, 512>>>(alns + i * CH, alnb + i * CH);
        k_ln_apply<<<applyGrid, 256>>>(O, X, CATh, CATl, CATDIM, i * CH, X, 1);
    }

    k_mma<0><<<gridF, 256, MMA_SMEM4>>>(CATh, CATl, CATDIM, Wfh, Wfl, CATDIM, bf,
                                        (float*)d_out, nullptr, nullptr, FDIM, CATDIM);
}